// round 8
// baseline (speedup 1.0000x reference)
#include <cuda_runtime.h>

#define F_CH   64
#define HW     4096
#define BATCH  32
#define NSTAT  14
#define GSIZE  64          // blocks per channel-group: 32 batches x 2 half-planes
#define HALFN  2048        // floats per half-plane

__device__ float g_part[F_CH * GSIZE * NSTAT];   // per-(f,sub) partial stats
__device__ unsigned int g_cnt[F_CH];             // monotonic ticket counters (zero-init)

__device__ __forceinline__ void acc4(float x0, float x1, float x2, float x3, float* s) {
    s[0] += x0; s[1] += x1; s[2] += x2; s[3] += x3;
    s[4]  = fmaf(x0, x0, s[4]);
    s[5]  = fmaf(x0, x1, s[5]);
    s[6]  = fmaf(x0, x2, s[6]);
    s[7]  = fmaf(x0, x3, s[7]);
    s[8]  = fmaf(x1, x1, s[8]);
    s[9]  = fmaf(x1, x2, s[9]);
    s[10] = fmaf(x1, x3, s[10]);
    s[11] = fmaf(x2, x3, s[11]);
    s[12] = fmaf(x2, x2, s[12]);
    s[13] = fmaf(x3, x3, s[13]);
}
// s: 0..3 sums; 4:00 5:01 6:02 7:03 8:11 9:12 10:13 11:23 12:22 13:33

__device__ __forceinline__ float4 mix4(float4 v0, float4 v1, float4 v2, float4 v3,
                                       float w0, float w1, float w2, float w3, float bb) {
    float4 o;
    o.x = fmaf(w0, v0.x, fmaf(w1, v1.x, fmaf(w2, v2.x, fmaf(w3, v3.x, bb))));
    o.y = fmaf(w0, v0.y, fmaf(w1, v1.y, fmaf(w2, v2.y, fmaf(w3, v3.y, bb))));
    o.z = fmaf(w0, v0.z, fmaf(w1, v1.z, fmaf(w2, v2.z, fmaf(w3, v3.z, bb))));
    o.w = fmaf(w0, v0.w, fmaf(w1, v1.w, fmaf(w2, v2.w, fmaf(w3, v3.w, bb))));
    return o;
}

// Single fused kernel: read x once, hold tile in registers across a
// per-channel-group ticket barrier, then apply whitening+affine and store.
__global__ __launch_bounds__(256) void fused_qbn(const float* __restrict__ x,
                                                 const float* __restrict__ weight,
                                                 const float* __restrict__ bias,
                                                 float* __restrict__ out) {
    const int bid  = blockIdx.x;         // groups of 64 contiguous bids per f
    const int f    = bid >> 6;           // 0..63
    const int sub  = bid & 63;           // 0..63
    const int bb   = sub >> 1;           // 0..31
    const int half = sub & 1;            // 0..1

    const size_t base = ((size_t)bb * 256 + f) * HW + (size_t)half * HALFN;
    const float4* __restrict__ p0 = (const float4*)(x + base);
    const float4* __restrict__ p1 = (const float4*)(x + base + (size_t)64  * HW);
    const float4* __restrict__ p2 = (const float4*)(x + base + (size_t)128 * HW);
    const float4* __restrict__ p3 = (const float4*)(x + base + (size_t)192 * HW);

    const int i0 = threadIdx.x;          // HALFN/4 = 512 float4; 2 per thread
    const int i1 = threadIdx.x + 256;

    // ---- Phase 1: load tile (held in registers) + accumulate stats ----
    float4 a0 = __ldcg(p0 + i0), a1 = __ldcg(p0 + i1);
    float4 b0 = __ldcg(p1 + i0), b1 = __ldcg(p1 + i1);
    float4 c0 = __ldcg(p2 + i0), c1 = __ldcg(p2 + i1);
    float4 d0 = __ldcg(p3 + i0), d1 = __ldcg(p3 + i1);

    float s[NSTAT];
#pragma unroll
    for (int k = 0; k < NSTAT; k++) s[k] = 0.f;
    acc4(a0.x, b0.x, c0.x, d0.x, s);  acc4(a0.y, b0.y, c0.y, d0.y, s);
    acc4(a0.z, b0.z, c0.z, d0.z, s);  acc4(a0.w, b0.w, c0.w, d0.w, s);
    acc4(a1.x, b1.x, c1.x, d1.x, s);  acc4(a1.y, b1.y, c1.y, d1.y, s);
    acc4(a1.z, b1.z, c1.z, d1.z, s);  acc4(a1.w, b1.w, c1.w, d1.w, s);

#pragma unroll
    for (int k = 0; k < NSTAT; k++) {
#pragma unroll
        for (int off = 16; off; off >>= 1)
            s[k] += __shfl_down_sync(0xffffffffu, s[k], off);
    }

    __shared__ float sm[8][NSTAT];
    __shared__ float AC[20];
    const int warp = threadIdx.x >> 5, lane = threadIdx.x & 31;
    if (lane == 0) {
#pragma unroll
        for (int k = 0; k < NSTAT; k++) sm[warp][k] = s[k];
    }
    __syncthreads();
    if (threadIdx.x < NSTAT) {
        float t = 0.f;
#pragma unroll
        for (int w = 0; w < 8; w++) t += sm[w][threadIdx.x];
        g_part[(f * GSIZE + sub) * NSTAT + threadIdx.x] = t;
        __threadfence();   // make partials globally visible before the ticket
    }
    __syncthreads();

    // ---- Ticket barrier (graph-replay safe: counter is monotonic forever) ----
    if (threadIdx.x == 0) {
        unsigned int t = atomicAdd(&g_cnt[f], 1u);
        unsigned int target = (t / GSIZE) * GSIZE + GSIZE;
        while (atomicAdd(&g_cnt[f], 0u) < target) { __nanosleep(64); }
    }
    __syncthreads();
    __threadfence();  // acquire: see all groups' partials

    // ---- Redundant per-block solve: reduce 64 partials, Cholesky, fold W,b ----
    if (threadIdx.x < 32) {
        float r[NSTAT];
        const float* pa = &g_part[(f * GSIZE + threadIdx.x) * NSTAT];
        const float* pb = &g_part[(f * GSIZE + threadIdx.x + 32) * NSTAT];
#pragma unroll
        for (int k = 0; k < NSTAT; k++) r[k] = pa[k] + pb[k];
#pragma unroll
        for (int k = 0; k < NSTAT; k++) {
#pragma unroll
            for (int off = 16; off; off >>= 1)
                r[k] += __shfl_down_sync(0xffffffffu, r[k], off);
        }
        if (threadIdx.x == 0) {
            const float invN = 1.0f / (float)(BATCH * HW);
            const float eps = 1e-5f;
            float m0 = r[0] * invN, m1 = r[1] * invN, m2 = r[2] * invN, m3 = r[3] * invN;
            float c00 = r[4]  * invN - m0 * m0 + eps;
            float c10 = r[5]  * invN - m0 * m1;
            float c20 = r[6]  * invN - m0 * m2;
            float c30 = r[7]  * invN - m0 * m3;
            float c11 = r[8]  * invN - m1 * m1 + eps;
            float c21 = r[9]  * invN - m1 * m2;
            float c31 = r[10] * invN - m1 * m3;
            float c32 = r[11] * invN - m2 * m3;
            float c22 = r[12] * invN - m2 * m2 + eps;
            float c33 = r[13] * invN - m3 * m3 + eps;

            float L00 = sqrtf(c00);
            float L10 = c10 / L00, L20 = c20 / L00, L30 = c30 / L00;
            float L11 = sqrtf(c11 - L10 * L10);
            float L21 = (c21 - L20 * L10) / L11;
            float L31 = (c31 - L30 * L10) / L11;
            float L22 = sqrtf(c22 - L20 * L20 - L21 * L21);
            float L32 = (c32 - L30 * L20 - L31 * L21) / L22;
            float L33 = sqrtf(c33 - L30 * L30 - L31 * L31 - L32 * L32);

            float i00 = 1.f / L00, i11 = 1.f / L11, i22 = 1.f / L22, i33 = 1.f / L33;
            float i10 = -(L10 * i00) * i11;
            float i20 = -(L20 * i00 + L21 * i10) * i22;
            float i21 = -(L21 * i11) * i22;
            float i30 = -(L30 * i00 + L31 * i10 + L32 * i20) * i33;
            float i31 = -(L31 * i11 + L32 * i21) * i33;
            float i32 = -(L32 * i22) * i33;

            float Linv[4][4] = {{i00, 0, 0, 0},
                                {i10, i11, 0, 0},
                                {i20, i21, i22, 0},
                                {i30, i31, i32, i33}};
            float m[4] = {m0, m1, m2, m3};
#pragma unroll
            for (int i = 0; i < 4; i++) {
                float A[4];
#pragma unroll
                for (int j = 0; j < 4; j++) {
                    float t2 = 0.f;
#pragma unroll
                    for (int k = 0; k < 4; k++)
                        if (k >= j) t2 = fmaf(weight[(i * 4 + k) * F_CH + f], Linv[k][j], t2);
                    A[j] = t2;
                    AC[i * 4 + j] = t2;
                }
                AC[16 + i] = bias[i * F_CH + f]
                           - (A[0] * m[0] + A[1] * m[1] + A[2] * m[2] + A[3] * m[3]);
            }
        }
    }
    __syncthreads();

    // ---- Phase 2: mix the register-held tile and store ----
    float a00 = AC[0],  a01 = AC[1],  a02 = AC[2],  a03 = AC[3];
    float a10 = AC[4],  a11 = AC[5],  a12 = AC[6],  a13 = AC[7];
    float a20 = AC[8],  a21 = AC[9],  a22 = AC[10], a23 = AC[11];
    float a30 = AC[12], a31 = AC[13], a32 = AC[14], a33 = AC[15];
    float k0 = AC[16], k1 = AC[17], k2 = AC[18], k3 = AC[19];

    float4* __restrict__ q0 = (float4*)(out + base);
    float4* __restrict__ q1 = (float4*)(out + base + (size_t)64  * HW);
    float4* __restrict__ q2 = (float4*)(out + base + (size_t)128 * HW);
    float4* __restrict__ q3 = (float4*)(out + base + (size_t)192 * HW);

    __stcs(q0 + i0, mix4(a0, b0, c0, d0, a00, a01, a02, a03, k0));
    __stcs(q1 + i0, mix4(a0, b0, c0, d0, a10, a11, a12, a13, k1));
    __stcs(q2 + i0, mix4(a0, b0, c0, d0, a20, a21, a22, a23, k2));
    __stcs(q3 + i0, mix4(a0, b0, c0, d0, a30, a31, a32, a33, k3));
    __stcs(q0 + i1, mix4(a1, b1, c1, d1, a00, a01, a02, a03, k0));
    __stcs(q1 + i1, mix4(a1, b1, c1, d1, a10, a11, a12, a13, k1));
    __stcs(q2 + i1, mix4(a1, b1, c1, d1, a20, a21, a22, a23, k2));
    __stcs(q3 + i1, mix4(a1, b1, c1, d1, a30, a31, a32, a33, k3));
}

extern "C" void kernel_launch(void* const* d_in, const int* in_sizes, int n_in,
                              void* d_out, int out_size) {
    const float* x      = (const float*)d_in[0];
    const float* weight = (const float*)d_in[1];
    const float* bias   = (const float*)d_in[2];
    float* out = (float*)d_out;

    fused_qbn<<<F_CH * GSIZE, 256>>>(x, weight, bias, out);
}